// round 15
// baseline (speedup 1.0000x reference)
#include <cuda_runtime.h>
#include <math.h>

// Problem constants (fixed shapes: x is (8,1,64,64) float32)
#define B_DIM 8
#define H_DIM 64
#define W_DIM 64
#define N_PIX (H_DIM * W_DIM)          // 4096
#define M0_CONST 0.01f

#define NOFF (127 * 127)               // 16129 offsets, sorted by d2
#define MAXD2 (63 * 63 * 2)
#define NCHT 16                        // chunks in hot loop (256 entries)
#define PREF 2                         // prefetch depth (double buffer)
#define HOTX ((NCHT + PREF) * 16)      // 288 staged entries (incl. slack)
#define HY 10                          // halo rows (top & bottom)
#define HX 12                          // halo cols left (right halo = 12)
#define PSTR 88                        // padded row stride (12+64+12)
#define PROWS 84                       // 10+64+10
#define PSZ (PROWS * PSTR)             // 7392 floats
#define ROW4 (PSTR / 4)                // 22 float4 per padded row
#define TOP4 (HY * ROW4)               // 220
#define BOT4 (HY * ROW4)               // 220
#define SIDE4 (H_DIM * 6)              // 384
#define HALO4 (TOP4 + BOT4 + SIDE4)    // 824

struct OffTable { unsigned int v[NOFF]; };

constexpr OffTable make_table() {
    OffTable t{};
    int bins[MAXD2 + 1] = {};
    for (int dy = -63; dy <= 63; ++dy)
        for (int dx = -63; dx <= 63; ++dx)
            bins[dy * dy + dx * dx]++;
    int acc = 0;
    for (int d = 0; d <= MAXD2; ++d) { int c = bins[d]; bins[d] = acc; acc += c; }
    for (int dy = -63; dy <= 63; ++dy)
        for (int dx = -63; dx <= 63; ++dx) {
            int d2 = dy * dy + dx * dx;
            t.v[bins[d2]++] = ((unsigned)d2 << 16)
                            | ((unsigned)(dy + 63) << 8)
                            | (unsigned)(dx + 63);
        }
    return t;
}

__device__ constexpr OffTable g_off = make_table();   // fallback path only

// Hot prefix as compile-time constants: padded-smem offset + float d2.
struct Hot { int c[HOTX]; float d2[HOTX]; };
constexpr Hot make_hot() {
    Hot h{};
    OffTable t = make_table();
    for (int k = 0; k < HOTX; ++k) {
        int dy = (int)((t.v[k] >> 8) & 255u) - 63;
        int dx = (int)(t.v[k] & 255u) - 63;
        h.c[k]  = (dy + HY) * PSTR + (dx + HX);
        h.d2[k] = (float)(t.v[k] >> 16);
    }
    return h;
}
__device__ constexpr Hot g_hot = make_hot();

// Halo must cover every staged entry: |dy| <= HY, |dx| <= HX.
constexpr bool halo_ok() {
    OffTable t = make_table();
    for (int k = 0; k < HOTX; ++k) {
        int dy = (int)((t.v[k] >> 8) & 255u) - 63;
        int dx = (int)(t.v[k] & 255u) - 63;
        if (dy < -HY || dy > HY || dx < -HX || dx > HX) return false;
    }
    return true;
}
static_assert(halo_ok(), "halo too small for HOTX prefix");

// Gather one 16-entry chunk; all addresses are [base + compile-time imm].
__device__ __forceinline__ void loadW(const float* __restrict__ pimg, int bi,
                                      int ch, float* w) {
    #pragma unroll
    for (int j = 0; j < 16; ++j)
        w[j] = pimg[bi + g_hot.c[ch * 16 + j]];
}

// Exact clipped evaluation of one chunk (R10-style: group-of-4 prefix clip,
// once saturated the clip yields exact zeros -> no-op, no branch needed).
__device__ __forceinline__ void proc16(const float* w, int ch, float& r,
                                       float& s0, float& s1,
                                       float& s2, float& s3) {
    #pragma unroll
    for (int g = 0; g < 4; ++g) {
        const int k = ch * 16 + g * 4;
        const float w0 = w[g * 4],     w1 = w[g * 4 + 1];
        const float w2 = w[g * 4 + 2], w3 = w[g * 4 + 3];
        const float p1 = w0;
        const float p2 = p1 + w1;
        const float p3 = p2 + w2;
        s0 = fmaf(fmaxf(0.f, fminf(w0, r)),      g_hot.d2[k],     s0);
        s1 = fmaf(fmaxf(0.f, fminf(w1, r - p1)), g_hot.d2[k + 1], s1);
        s2 = fmaf(fmaxf(0.f, fminf(w2, r - p2)), g_hot.d2[k + 2], s2);
        s3 = fmaf(fmaxf(0.f, fminf(w3, r - p3)), g_hot.d2[k + 3], s3);
        r -= (p3 + w3);                 // only cross-entry dependence
    }
}

// One block = 4 strided rows (slab, slab+16, +32, +48) of one image.
// Image lives zero-padded in smem; hot loop is LDS [R+imm] only.
__global__ __launch_bounds__(256) void dtm_kernel(const float* __restrict__ xin,
                                                  float* __restrict__ out) {
    __shared__ __align__(16) float pimg[PSZ];
    __shared__ float swarp[8];

    const int tid   = threadIdx.x;
    const int lane  = tid & 31;
    const int wid   = tid >> 5;
    const int batch = blockIdx.x >> 4;
    const int slab  = blockIdx.x & 15;
    const float* img = xin + batch * N_PIX;

    // Image loads first (long latency).
    const float4 v0 = ((const float4*)img)[tid];
    const float4 v1 = ((const float4*)img)[tid + 256];
    const float4 v2 = ((const float4*)img)[tid + 512];
    const float4 v3 = ((const float4*)img)[tid + 768];

    // Zero ONLY the halo (disjoint from the scattered interior -> no race,
    // so one barrier covers zeroing + scatter + reduction partials).
    {
        const float4 z4 = make_float4(0.f, 0.f, 0.f, 0.f);
        #pragma unroll
        for (int it = 0; it < 4; ++it) {
            const int i = tid + it * 256;
            if (i < HALO4) {
                int fi;
                if (i < TOP4)              fi = i;
                else if (i < TOP4 + BOT4)  fi = (i - TOP4) + (HY + H_DIM) * ROW4;
                else {
                    const int j   = i - (TOP4 + BOT4);      // 0..383
                    const int row = HY + j / 6;
                    const int k   = j - (j / 6) * 6;        // 0..5
                    const int c4  = (k < 3) ? k : (16 + k); // {0,1,2,19,20,21}
                    fi = row * ROW4 + c4;
                }
                ((float4*)pimg)[fi] = z4;
            }
        }
    }

    // Scatter image into padded layout (interior only, 16B-aligned).
    const int y0 = tid >> 4;
    const int x0 = (tid & 15) << 2;
    *(float4*)&pimg[(y0 + HY)      * PSTR + x0 + HX] = v0;
    *(float4*)&pimg[(y0 + HY + 16) * PSTR + x0 + HX] = v1;
    *(float4*)&pimg[(y0 + HY + 32) * PSTR + x0 + HX] = v2;
    *(float4*)&pimg[(y0 + HY + 48) * PSTR + x0 + HX] = v3;

    float part = ((v0.x + v0.y) + (v0.z + v0.w)) + ((v1.x + v1.y) + (v1.z + v1.w))
               + ((v2.x + v2.y) + (v2.z + v2.w)) + ((v3.x + v3.y) + (v3.z + v3.w));
    #pragma unroll
    for (int o = 16; o > 0; o >>= 1)
        part += __shfl_xor_sync(0xFFFFFFFFu, part, o);
    if (lane == 0) swarp[wid] = part;

    __syncthreads();                              // the ONLY barrier

    const int x = tid & 63;
    const int y = slab + ((tid >> 6) << 4);       // strided row assignment
    const int bi = y * PSTR + x;

    // First gathers don't depend on m -> issue immediately after barrier.
    float wA[16], wB[16];
    loadW(pimg, bi, 0, wA);
    loadW(pimg, bi, 1, wB);

    float total;
    {
        float4 a = ((const float4*)swarp)[0];
        float4 b = ((const float4*)swarp)[1];
        total = ((a.x + a.y) + (a.z + a.w)) + ((b.x + b.y) + (b.z + b.w));
    }
    const float m = M0_CONST * total;

    float r = m;
    float s0 = 0.f, s1 = 0.f, s2 = 0.f, s3 = 0.f;
    bool done = false;

    if (m > 0.0f) {
        // proc(k) -> prefetch(k+2 into k's buffer) -> vote: chunk k+2's LDS
        // latency hides under chunk k's vote/branch and chunk k+1's FP.
        #define STEP(ch, BUF) if (!done) {                                 \
            proc16(BUF, ch, r, s0, s1, s2, s3);                            \
            if ((ch) + PREF < NCHT + PREF) loadW(pimg, bi, (ch) + PREF, BUF); \
            if (__all_sync(0xFFFFFFFFu, r <= 0.f)) done = true;            \
        }
        STEP(0, wA);  STEP(1, wB);  STEP(2, wA);  STEP(3, wB);
        STEP(4, wA);  STEP(5, wB);  STEP(6, wA);  STEP(7, wB);
        STEP(8, wA);  STEP(9, wB);  STEP(10, wA); STEP(11, wB);
        STEP(12, wA); STEP(13, wB); STEP(14, wA); STEP(15, wB);
        #undef STEP

        // Fallback past the hot prefix (pathological inputs only).
        if (!done && __any_sync(0xFFFFFFFFu, r > 0.f)) {
            for (int k = NCHT * 16; k < NOFF; ++k) {
                const unsigned p = g_off.v[k];
                const int ny = y + (int)((p >> 8) & 255u) - 63;
                const int nx = x + (int)(p & 255u) - 63;
                if ((unsigned)ny < (unsigned)H_DIM &&
                    (unsigned)nx < (unsigned)W_DIM) {
                    const float w   = img[(ny << 6) | nx];
                    const float eff = fmaxf(0.f, fminf(w, r));
                    s0 = fmaf(eff, (float)(p >> 16), s0);
                    r -= w;
                }
                if (__all_sync(0xFFFFFFFFu, r <= 0.f)) break;
            }
        }
    }

    const float s = (s0 + s1) + (s2 + s3);
    const float result = (total > 0.0f) ? sqrtf(s / m) : 0.0f;
    out[batch * N_PIX + (y << 6) + x] = result;
}

extern "C" void kernel_launch(void* const* d_in, const int* in_sizes, int n_in,
                              void* d_out, int out_size) {
    const float* xin = (const float*)d_in[0];
    float* out = (float*)d_out;
    (void)in_sizes; (void)n_in; (void)out_size;
    dtm_kernel<<<B_DIM * (N_PIX / 256), 256>>>(xin, out);
}

// round 17
// speedup vs baseline: 1.3116x; 1.3116x over previous
#include <cuda_runtime.h>
#include <math.h>

// Problem constants (fixed shapes: x is (8,1,64,64) float32)
#define B_DIM 8
#define H_DIM 64
#define W_DIM 64
#define N_PIX (H_DIM * W_DIM)          // 4096
#define M0_CONST 0.01f

#define NOFF (127 * 127)               // 16129 offsets, sorted by d2
#define MAXD2 (63 * 63 * 2)
#define NCHT 16                        // chunks in hot loop (256 entries)
#define PREF 2                         // prefetch depth (double buffer)
#define HOTX ((NCHT + PREF) * 16)      // 288 staged entries (incl. slack)
#define HY 10                          // halo rows (top & bottom)
#define HX 12                          // halo cols left (right halo = 12)
#define PSTR 88                        // padded row stride (12+64+12)
#define PROWS 84                       // 10+64+10
#define PSZ (PROWS * PSTR)             // 7392 floats
#define ROW4 (PSTR / 4)                // 22 float4 per padded row
#define TOP4 (HY * ROW4)               // 220
#define BOT4 (HY * ROW4)               // 220
#define SIDE4 (H_DIM * 6)              // 384
#define HALO4 (TOP4 + BOT4 + SIDE4)    // 824

struct OffTable { unsigned int v[NOFF]; };

constexpr OffTable make_table() {
    OffTable t{};
    int bins[MAXD2 + 1] = {};
    for (int dy = -63; dy <= 63; ++dy)
        for (int dx = -63; dx <= 63; ++dx)
            bins[dy * dy + dx * dx]++;
    int acc = 0;
    for (int d = 0; d <= MAXD2; ++d) { int c = bins[d]; bins[d] = acc; acc += c; }
    for (int dy = -63; dy <= 63; ++dy)
        for (int dx = -63; dx <= 63; ++dx) {
            int d2 = dy * dy + dx * dx;
            t.v[bins[d2]++] = ((unsigned)d2 << 16)
                            | ((unsigned)(dy + 63) << 8)
                            | (unsigned)(dx + 63);
        }
    return t;
}

__device__ constexpr OffTable g_off = make_table();   // fallback path only

// Hot prefix as compile-time constants: padded-smem offset + float d2.
struct Hot { int c[HOTX]; float d2[HOTX]; };
constexpr Hot make_hot() {
    Hot h{};
    OffTable t = make_table();
    for (int k = 0; k < HOTX; ++k) {
        int dy = (int)((t.v[k] >> 8) & 255u) - 63;
        int dx = (int)(t.v[k] & 255u) - 63;
        h.c[k]  = (dy + HY) * PSTR + (dx + HX);
        h.d2[k] = (float)(t.v[k] >> 16);
    }
    return h;
}
__device__ constexpr Hot g_hot = make_hot();

// Halo must cover every staged entry: |dy| <= HY, |dx| <= HX.
constexpr bool halo_ok() {
    OffTable t = make_table();
    for (int k = 0; k < HOTX; ++k) {
        int dy = (int)((t.v[k] >> 8) & 255u) - 63;
        int dx = (int)(t.v[k] & 255u) - 63;
        if (dy < -HY || dy > HY || dx < -HX || dx > HX) return false;
    }
    return true;
}
static_assert(halo_ok(), "halo too small for HOTX prefix");

// Gather one 16-entry chunk; all addresses are [base + compile-time imm].
__device__ __forceinline__ void loadW(const float* __restrict__ pimg, int bi,
                                      int ch, float* w) {
    #pragma unroll
    for (int j = 0; j < 16; ++j)
        w[j] = pimg[bi + g_hot.c[ch * 16 + j]];
}

// Exact clipped evaluation of one chunk (group-of-4 prefix clip; once
// saturated the clip yields exact zeros -> no-op, no branch needed).
__device__ __forceinline__ void proc16(const float* w, int ch, float& r,
                                       float& s0, float& s1,
                                       float& s2, float& s3) {
    #pragma unroll
    for (int g = 0; g < 4; ++g) {
        const int k = ch * 16 + g * 4;
        const float w0 = w[g * 4],     w1 = w[g * 4 + 1];
        const float w2 = w[g * 4 + 2], w3 = w[g * 4 + 3];
        const float p1 = w0;
        const float p2 = p1 + w1;
        const float p3 = p2 + w2;
        s0 = fmaf(fmaxf(0.f, fminf(w0, r)),      g_hot.d2[k],     s0);
        s1 = fmaf(fmaxf(0.f, fminf(w1, r - p1)), g_hot.d2[k + 1], s1);
        s2 = fmaf(fmaxf(0.f, fminf(w2, r - p2)), g_hot.d2[k + 2], s2);
        s3 = fmaf(fmaxf(0.f, fminf(w3, r - p3)), g_hot.d2[k + 3], s3);
        r -= (p3 + w3);                 // only cross-entry dependence
    }
}

// One block = 4 strided rows (slab, slab+16, +32, +48) of one image.
// Image lives zero-padded in smem; hot loop is LDS [R+imm] only.
__global__ __launch_bounds__(256) void dtm_kernel(const float* __restrict__ xin,
                                                  float* __restrict__ out) {
    __shared__ __align__(16) float pimg[PSZ];
    __shared__ float swarp[8];

    const int tid   = threadIdx.x;
    const int lane  = tid & 31;
    const int wid   = tid >> 5;
    const int batch = blockIdx.x >> 4;
    const int slab  = blockIdx.x & 15;
    const float* img = xin + batch * N_PIX;

    // Image loads first (long latency).
    const float4 v0 = ((const float4*)img)[tid];
    const float4 v1 = ((const float4*)img)[tid + 256];
    const float4 v2 = ((const float4*)img)[tid + 512];
    const float4 v3 = ((const float4*)img)[tid + 768];

    // Zero ONLY the halo (disjoint from the scattered interior -> no race,
    // so one barrier covers zeroing + scatter + reduction partials).
    {
        const float4 z4 = make_float4(0.f, 0.f, 0.f, 0.f);
        #pragma unroll
        for (int it = 0; it < 4; ++it) {
            const int i = tid + it * 256;
            if (i < HALO4) {
                int fi;
                if (i < TOP4)              fi = i;
                else if (i < TOP4 + BOT4)  fi = (i - TOP4) + (HY + H_DIM) * ROW4;
                else {
                    const int j   = i - (TOP4 + BOT4);      // 0..383
                    const int row = HY + j / 6;
                    const int k   = j - (j / 6) * 6;        // 0..5
                    const int c4  = (k < 3) ? k : (16 + k); // {0,1,2,19,20,21}
                    fi = row * ROW4 + c4;
                }
                ((float4*)pimg)[fi] = z4;
            }
        }
    }

    // Scatter image into padded layout (interior only, 16B-aligned).
    const int y0 = tid >> 4;
    const int x0 = (tid & 15) << 2;
    *(float4*)&pimg[(y0 + HY)      * PSTR + x0 + HX] = v0;
    *(float4*)&pimg[(y0 + HY + 16) * PSTR + x0 + HX] = v1;
    *(float4*)&pimg[(y0 + HY + 32) * PSTR + x0 + HX] = v2;
    *(float4*)&pimg[(y0 + HY + 48) * PSTR + x0 + HX] = v3;

    float part = ((v0.x + v0.y) + (v0.z + v0.w)) + ((v1.x + v1.y) + (v1.z + v1.w))
               + ((v2.x + v2.y) + (v2.z + v2.w)) + ((v3.x + v3.y) + (v3.z + v3.w));
    #pragma unroll
    for (int o = 16; o > 0; o >>= 1)
        part += __shfl_xor_sync(0xFFFFFFFFu, part, o);
    if (lane == 0) swarp[wid] = part;

    __syncthreads();                              // the ONLY barrier

    const int x = tid & 63;
    const int y = slab + ((tid >> 6) << 4);       // strided row assignment
    const int bi = y * PSTR + x;

    // First gathers don't depend on m -> issue immediately after barrier.
    float wA[16], wB[16];
    loadW(pimg, bi, 0, wA);
    loadW(pimg, bi, 1, wB);

    float total;
    {
        float4 a = ((const float4*)swarp)[0];
        float4 b = ((const float4*)swarp)[1];
        total = ((a.x + a.y) + (a.z + a.w)) + ((b.x + b.y) + (b.z + b.w));
    }
    const float m = M0_CONST * total;

    float r = m;
    float s0 = 0.f, s1 = 0.f, s2 = 0.f, s3 = 0.f;

    if (m > 0.0f) {
        // Pairs of chunks between votes; warp-uniform goto on saturation
        // (no carried done-predicate -> no BSSY/BSYNC chains). Prefetch
        // chunk ch+2 into the buffer just consumed.
        #define PAIR(c0)                                                   \
            proc16(wA, (c0), r, s0, s1, s2, s3);                           \
            loadW(pimg, bi, (c0) + 2, wA);                                 \
            proc16(wB, (c0) + 1, r, s0, s1, s2, s3);                       \
            loadW(pimg, bi, (c0) + 3, wB);                                 \
            if (__all_sync(0xFFFFFFFFu, r <= 0.f)) goto hot_done;
        PAIR(0)  PAIR(2)  PAIR(4)  PAIR(6)
        PAIR(8)  PAIR(10) PAIR(12)
        #undef PAIR
        // Last pair: no prefetch needed.
        proc16(wA, 14, r, s0, s1, s2, s3);
        proc16(wB, 15, r, s0, s1, s2, s3);
        if (__all_sync(0xFFFFFFFFu, r <= 0.f)) goto hot_done;

        // Fallback past the hot prefix (pathological inputs only).
        if (__any_sync(0xFFFFFFFFu, r > 0.f)) {
            for (int k = NCHT * 16; k < NOFF; ++k) {
                const unsigned p = g_off.v[k];
                const int ny = y + (int)((p >> 8) & 255u) - 63;
                const int nx = x + (int)(p & 255u) - 63;
                if ((unsigned)ny < (unsigned)H_DIM &&
                    (unsigned)nx < (unsigned)W_DIM) {
                    const float w   = img[(ny << 6) | nx];
                    const float eff = fmaxf(0.f, fminf(w, r));
                    s0 = fmaf(eff, (float)(p >> 16), s0);
                    r -= w;
                }
                if (__all_sync(0xFFFFFFFFu, r <= 0.f)) break;
            }
        }
        hot_done: ;
    }

    const float s = (s0 + s1) + (s2 + s3);
    const float result = (total > 0.0f) ? sqrtf(s / m) : 0.0f;
    out[batch * N_PIX + (y << 6) + x] = result;
}

extern "C" void kernel_launch(void* const* d_in, const int* in_sizes, int n_in,
                              void* d_out, int out_size) {
    const float* xin = (const float*)d_in[0];
    float* out = (float*)d_out;
    (void)in_sizes; (void)n_in; (void)out_size;
    dtm_kernel<<<B_DIM * (N_PIX / 256), 256>>>(xin, out);
}